// round 12
// baseline (speedup 1.0000x reference)
#include <cuda_runtime.h>
#include <cuda_fp16.h>
#include <cstdint>

// GraphLearning, R12: periphery harvest on top of the R11 structure.
//  - prep fused into convert (one launch)
//  - edge kernel: 2 edges/thread, int2/float2 vectorized, MLP-friendly
//  - GEMM: issue-before-wait (cp.async wait_group 2 pattern)
// hidden_cat = feat @ B, B[d, g*128+h] = att[g,d]*Wlin[g,d,h]; a_l/a_r fused in epilogue.

#define NMAX   100000
#define NPAD   100096           // 782 * 128
#define D_IN   512
#define GDIM   4
#define HDIM   128
#define BM     128
#define KC     32
#define NIT    (D_IN / KC)      // 16
#define ASTRB  80               // smem row stride bytes (40 fp16) -> conflict-free ldmatrix

#define PREP_BLOCKS  1024       // 262144 / 256
#define CONV_BLOCKS  25024      // NPAD*D_IN/8/256

__device__ __half g_feat_h[(size_t)NPAD * D_IN];     // fp16 features, padded (102.5 MB)
__device__ __half g_Bh[GDIM * HDIM * D_IN];          // B pre-transposed [g][n][k] fp16
__device__ float4 g_al[NMAX];
__device__ float4 g_ar[NMAX];

// ---------------- helpers ----------------
__device__ __forceinline__ uint32_t smem_u32(const void* p) {
    uint32_t a;
    asm("{ .reg .u64 t; cvta.to.shared.u64 t, %1; cvt.u32.u64 %0, t; }" : "=r"(a) : "l"(p));
    return a;
}
__device__ __forceinline__ void ldsm4(uint32_t& r0, uint32_t& r1, uint32_t& r2, uint32_t& r3,
                                      uint32_t addr) {
    asm volatile("ldmatrix.sync.aligned.m8n8.x4.shared.b16 {%0,%1,%2,%3}, [%4];"
                 : "=r"(r0), "=r"(r1), "=r"(r2), "=r"(r3) : "r"(addr));
}
__device__ __forceinline__ void mma16816(float* c, const uint32_t* a, uint32_t b0, uint32_t b1) {
    asm volatile("mma.sync.aligned.m16n8k16.row.col.f32.f16.f16.f32 "
                 "{%0,%1,%2,%3}, {%4,%5,%6,%7}, {%8,%9}, {%0,%1,%2,%3};"
                 : "+f"(c[0]), "+f"(c[1]), "+f"(c[2]), "+f"(c[3])
                 : "r"(a[0]), "r"(a[1]), "r"(a[2]), "r"(a[3]), "r"(b0), "r"(b1));
}
__device__ __forceinline__ void cp16(uint32_t dst, const void* src) {
    asm volatile("cp.async.cg.shared.global [%0], [%1], 16;" :: "r"(dst), "l"(src));
}
#define CP_COMMIT() asm volatile("cp.async.commit_group;" ::: "memory")
#define CP_WAIT2()  asm volatile("cp.async.wait_group 2;" ::: "memory")

__device__ __forceinline__ uint32_t pack_h2(__half a, __half b) {
    __half2 t; t.x = a; t.y = b;
    return *reinterpret_cast<uint32_t*>(&t);
}
__device__ __forceinline__ float sigmoidf_(float x) {
    return 1.f / (1.f + __expf(-x));
}

// ---------------- fused prep (B) + convert (A fp32->fp16, zero-pad) ----------------
__global__ void prep_convert_kernel(const float* __restrict__ att,
                                    const float* __restrict__ Wlin,
                                    const float* __restrict__ feat, int N) {
    if (blockIdx.x < PREP_BLOCKS) {
        int i = blockIdx.x * blockDim.x + threadIdx.x;    // [g][d][h] flat
        int g = i >> 16, d = (i >> 7) & 511, n = i & 127;
        float w = att[g * D_IN + d] * Wlin[i];
        g_Bh[(size_t)g * (HDIM * D_IN) + (size_t)n * D_IN + d] = __float2half_rn(w);
        return;
    }
    size_t i = ((size_t)(blockIdx.x - PREP_BLOCKS) * blockDim.x + threadIdx.x) * 8;
    if (i >= (size_t)NPAD * D_IN) return;
    uint4 v = make_uint4(0u, 0u, 0u, 0u);
    if (i < (size_t)N * D_IN) {
        float4 a = *reinterpret_cast<const float4*>(feat + i);
        float4 b = *reinterpret_cast<const float4*>(feat + i + 4);
        v = make_uint4(pack_h2(__float2half_rn(a.x), __float2half_rn(a.y)),
                       pack_h2(__float2half_rn(a.z), __float2half_rn(a.w)),
                       pack_h2(__float2half_rn(b.x), __float2half_rn(b.y)),
                       pack_h2(__float2half_rn(b.z), __float2half_rn(b.w)));
    }
    *reinterpret_cast<uint4*>(g_feat_h + i) = v;
}

// ---------------- GEMM: 256 thr, 2(m)x4(n) warps, warp tile m64n32, cp.async 3-stage ----
// stage: A 128x80B = 10240 | B 128x80B = 10240 -> 20480/stage, 3 stages = 61440 B
#define STG_SZ 20480
#define T_B    10240
#define SM_SZ  (3 * STG_SZ)

__global__ __launch_bounds__(256, 2)
void gemm_kernel(const float* __restrict__ b_lin,
                 const float* __restrict__ w_al, const float* __restrict__ b_al,
                 const float* __restrict__ w_ar, const float* __restrict__ b_ar,
                 float* __restrict__ out_hidden, int N) {
    extern __shared__ __align__(16) char sm[];
    const uint32_t sb = smem_u32(sm);

    const int tid = threadIdx.x, wid = tid >> 5, lid = tid & 31;
    const int wm = wid & 1, wn = wid >> 1;          // warp grid 2(m) x 4(n)
    const int g = blockIdx.x;
    const int row0 = blockIdx.y * BM;

    // loader mapping: unit u -> (row = u>>2, 16B quarter q = u&3); 512 units per tile
    const int lr0 = tid >> 2, lq = tid & 3;
    const __half* asrc = g_feat_h + (size_t)(row0 + lr0) * D_IN + lq * 8;
    const __half* asrc2 = asrc + (size_t)64 * D_IN;                 // rows 64..127
    const __half* bsrc = g_Bh + (size_t)g * (HDIM * D_IN) + (size_t)lr0 * D_IN + lq * 8;
    const __half* bsrc2 = bsrc + (size_t)64 * D_IN;
    const uint32_t dA1 = (uint32_t)lr0 * ASTRB + (uint32_t)lq * 16;
    const uint32_t dA2 = dA1 + 64 * ASTRB;

    auto issue = [&](int kchunk, uint32_t base) {
        int ko = kchunk * KC;
        cp16(base + dA1,       asrc  + ko);
        cp16(base + dA2,       asrc2 + ko);
        cp16(base + T_B + dA1, bsrc  + ko);
        cp16(base + T_B + dA2, bsrc2 + ko);
    };

    // preload stages 0,1
    issue(0, sb);            CP_COMMIT();
    issue(1, sb + STG_SZ);   CP_COMMIT();

    float c[4][4][4];
#pragma unroll
    for (int mi = 0; mi < 4; mi++)
#pragma unroll
        for (int ni = 0; ni < 4; ni++)
#pragma unroll
            for (int j = 0; j < 4; j++) c[mi][ni][j] = 0.f;

    const uint32_t lrs = (uint32_t)(lid & 15);      // ldmatrix row select
    const uint32_t lkh = (uint32_t)(lid >> 4) * 16; // k half offset (bytes)

    int bufidx = 0;
    for (int it = 0; it < NIT; it++) {
        // issue stage it+2 into the buffer consumed at iter it-1 (safe), then wait
        if (it + 2 < NIT) {
            int nb = bufidx + 2; if (nb >= 3) nb -= 3;
            issue(it + 2, sb + (uint32_t)nb * STG_SZ);
        }
        CP_COMMIT();                                 // uniform group counting (may be empty)
        CP_WAIT2();                                  // ensures stage `it` complete
        __syncthreads();
        const uint32_t cur = sb + (uint32_t)bufidx * STG_SZ;
        // compute: 2 ksteps of 16
#pragma unroll
        for (int ks = 0; ks < 2; ks++) {
            const uint32_t koff = (uint32_t)ks * 32 + lkh;
            uint32_t aA[4][4];
#pragma unroll
            for (int mi = 0; mi < 4; mi++) {
                uint32_t ra = (uint32_t)(wm * 64 + mi * 16) + lrs;
                ldsm4(aA[mi][0], aA[mi][1], aA[mi][2], aA[mi][3],
                      cur + ra * ASTRB + koff);
            }
            uint32_t bB[4][2];
#pragma unroll
            for (int p = 0; p < 2; p++) {
                uint32_t rb = (uint32_t)(wn * 32 + p * 16) + lrs;
                uint32_t r0, r1, r2, r3;
                ldsm4(r0, r1, r2, r3, cur + T_B + rb * ASTRB + koff);
                bB[2 * p][0] = r0; bB[2 * p][1] = r2;
                bB[2 * p + 1][0] = r1; bB[2 * p + 1][1] = r3;
            }
#pragma unroll
            for (int mi = 0; mi < 4; mi++)
#pragma unroll
                for (int ni = 0; ni < 4; ni++)
                    mma16816(c[mi][ni], aA[mi], bB[ni][0], bB[ni][1]);
        }
        if (++bufidx == 3) bufidx = 0;
        if (it + 1 < NIT) __syncthreads();           // LDSM of `cur` done before reuse window
    }

    // ---------------- epilogue ----------------
    __syncthreads();                    // all LDSM done; reuse smem for reductions
    float* laR = reinterpret_cast<float*>(sm);            // [4][128]
    float* raR = reinterpret_cast<float*>(sm + 2048);

    const int quad = lid >> 2, tq = lid & 3;
    const float* bl  = b_lin + g * HDIM;
    const float* wal = w_al + g * HDIM;
    const float* war = w_ar + g * HDIM;

#pragma unroll
    for (int mi = 0; mi < 4; mi++)
#pragma unroll
        for (int h = 0; h < 2; h++) {
            int rl = wm * 64 + mi * 16 + h * 8 + quad;
            int rg = row0 + rl;
            bool ok = rg < N;
            float la = 0.f, ra = 0.f;
            float* dst = out_hidden + (size_t)rg * (GDIM * HDIM) + g * HDIM;
#pragma unroll
            for (int ni = 0; ni < 4; ni++) {
                int col = wn * 32 + ni * 8 + tq * 2;
                float v0 = c[mi][ni][h * 2 + 0] + __ldg(bl + col);
                float v1 = c[mi][ni][h * 2 + 1] + __ldg(bl + col + 1);
                la += v0 * __ldg(wal + col) + v1 * __ldg(wal + col + 1);
                ra += v0 * __ldg(war + col) + v1 * __ldg(war + col + 1);
                if (ok) *reinterpret_cast<float2*>(dst + col) = make_float2(v0, v1);
            }
            la += __shfl_xor_sync(0xffffffffu, la, 1);
            la += __shfl_xor_sync(0xffffffffu, la, 2);
            ra += __shfl_xor_sync(0xffffffffu, ra, 1);
            ra += __shfl_xor_sync(0xffffffffu, ra, 2);
            if (tq == 0) { laR[wn * 128 + rl] = la; raR[wn * 128 + rl] = ra; }
        }
    __syncthreads();
    if (tid < 128) {
        int rg = row0 + tid;
        if (rg < N) {
            float la = laR[tid] + laR[128 + tid] + laR[256 + tid] + laR[384 + tid];
            float ra = raR[tid] + raR[128 + tid] + raR[256 + tid] + raR[384 + tid];
            reinterpret_cast<float*>(g_al)[rg * 4 + g] = la + b_al[g];
            reinterpret_cast<float*>(g_ar)[rg * 4 + g] = ra + b_ar[g];
        }
    }
}

// ---------------- edge factors: 2 edges/thread, vectorized ----------------
__global__ void edge_kernel(const int* __restrict__ src,
                            const int* __restrict__ dst,
                            float* __restrict__ factors, int E, int N) {
    const size_t P = (size_t)E >> 1;                 // edge pairs
    const size_t stride = (size_t)gridDim.x * blockDim.x;
    for (size_t p = (size_t)blockIdx.x * blockDim.x + threadIdx.x; p < P; p += stride) {
        int2 s2 = reinterpret_cast<const int2*>(src)[p];
        int2 d2 = reinterpret_cast<const int2*>(dst)[p];
        int s0 = min(max(s2.x, 0), N - 1), s1 = min(max(s2.y, 0), N - 1);
        int d0 = min(max(d2.x, 0), N - 1), d1 = min(max(d2.y, 0), N - 1);
        float4 l0 = g_al[s0], l1 = g_al[s1];
        float4 r0 = g_ar[d0], r1 = g_ar[d1];
        size_t e = p * 2;
        reinterpret_cast<float2*>(factors + e)[0] =
            make_float2(sigmoidf_(l0.x + r0.x), sigmoidf_(l1.x + r1.x));
        reinterpret_cast<float2*>(factors + (size_t)E + e)[0] =
            make_float2(sigmoidf_(l0.y + r0.y), sigmoidf_(l1.y + r1.y));
        reinterpret_cast<float2*>(factors + (size_t)2 * E + e)[0] =
            make_float2(sigmoidf_(l0.z + r0.z), sigmoidf_(l1.z + r1.z));
        reinterpret_cast<float2*>(factors + (size_t)3 * E + e)[0] =
            make_float2(sigmoidf_(l0.w + r0.w), sigmoidf_(l1.w + r1.w));
    }
    // odd-E tail (defensive; E is even in this dataset)
    if ((E & 1) && blockIdx.x == 0 && threadIdx.x == 0) {
        int e = E - 1;
        int s = min(max(src[e], 0), N - 1);
        int d = min(max(dst[e], 0), N - 1);
        float4 l = g_al[s], r = g_ar[d];
        factors[e]                 = sigmoidf_(l.x + r.x);
        factors[(size_t)E + e]     = sigmoidf_(l.y + r.y);
        factors[(size_t)2 * E + e] = sigmoidf_(l.z + r.z);
        factors[(size_t)3 * E + e] = sigmoidf_(l.w + r.w);
    }
}

// ---------------- launch ----------------
extern "C" void kernel_launch(void* const* d_in, const int* in_sizes, int n_in,
                              void* d_out, int out_size) {
    const float* feat  = (const float*)d_in[0];
    const int*   src   = (const int*)d_in[1];
    const int*   dst   = (const int*)d_in[2];
    const float* att   = (const float*)d_in[3];
    const float* Wlin  = (const float*)d_in[4];
    const float* b_lin = (const float*)d_in[5];
    const float* w_al  = (const float*)d_in[6];
    const float* b_al  = (const float*)d_in[7];
    const float* w_ar  = (const float*)d_in[8];
    const float* b_ar  = (const float*)d_in[9];

    int N = in_sizes[0] / D_IN;
    int E = in_sizes[1];
    float* out     = (float*)d_out;
    float* factors = out + (size_t)N * (GDIM * HDIM);

    cudaFuncSetAttribute(gemm_kernel, cudaFuncAttributeMaxDynamicSharedMemorySize, SM_SZ);

    prep_convert_kernel<<<PREP_BLOCKS + CONV_BLOCKS, 256>>>(att, Wlin, feat, N);

    dim3 grid(GDIM, (NPAD + BM - 1) / BM);   // g fastest: CTAs sharing feat rows adjacent in wave
    gemm_kernel<<<grid, 256, SM_SZ>>>(b_lin, w_al, b_al, w_ar, b_ar, out, N);

    edge_kernel<<<4096, 256>>>(src, dst, factors, E, N);
}

// round 16
// speedup vs baseline: 1.0318x; 1.0318x over previous
#include <cuda_runtime.h>
#include <cuda_fp16.h>
#include <cstdint>

// GraphLearning, R13: revert GEMM loop to R11 ordering (wait -> sync -> issue-under-compute,
// ONE barrier per iter); keep fused prep+convert; vectorized edge with full-coverage grid.
// hidden_cat = feat @ B, B[d, g*128+h] = att[g,d]*Wlin[g,d,h]; a_l/a_r fused in epilogue.

#define NMAX   100000
#define NPAD   100096           // 782 * 128
#define D_IN   512
#define GDIM   4
#define HDIM   128
#define BM     128
#define KC     32
#define NIT    (D_IN / KC)      // 16
#define ASTRB  80               // smem row stride bytes (40 fp16) -> conflict-free ldmatrix

#define PREP_BLOCKS  1024       // 262144 / 256
#define CONV_BLOCKS  25024      // NPAD*D_IN/8/256

__device__ __half g_feat_h[(size_t)NPAD * D_IN];     // fp16 features, padded (102.5 MB)
__device__ __half g_Bh[GDIM * HDIM * D_IN];          // B pre-transposed [g][n][k] fp16
__device__ float4 g_al[NMAX];
__device__ float4 g_ar[NMAX];

// ---------------- helpers ----------------
__device__ __forceinline__ uint32_t smem_u32(const void* p) {
    uint32_t a;
    asm("{ .reg .u64 t; cvta.to.shared.u64 t, %1; cvt.u32.u64 %0, t; }" : "=r"(a) : "l"(p));
    return a;
}
__device__ __forceinline__ void ldsm4(uint32_t& r0, uint32_t& r1, uint32_t& r2, uint32_t& r3,
                                      uint32_t addr) {
    asm volatile("ldmatrix.sync.aligned.m8n8.x4.shared.b16 {%0,%1,%2,%3}, [%4];"
                 : "=r"(r0), "=r"(r1), "=r"(r2), "=r"(r3) : "r"(addr));
}
__device__ __forceinline__ void mma16816(float* c, const uint32_t* a, uint32_t b0, uint32_t b1) {
    asm volatile("mma.sync.aligned.m16n8k16.row.col.f32.f16.f16.f32 "
                 "{%0,%1,%2,%3}, {%4,%5,%6,%7}, {%8,%9}, {%0,%1,%2,%3};"
                 : "+f"(c[0]), "+f"(c[1]), "+f"(c[2]), "+f"(c[3])
                 : "r"(a[0]), "r"(a[1]), "r"(a[2]), "r"(a[3]), "r"(b0), "r"(b1));
}
__device__ __forceinline__ void cp16(uint32_t dst, const void* src) {
    asm volatile("cp.async.cg.shared.global [%0], [%1], 16;" :: "r"(dst), "l"(src));
}
#define CP_COMMIT() asm volatile("cp.async.commit_group;" ::: "memory")
#define CP_WAIT1()  asm volatile("cp.async.wait_group 1;" ::: "memory")

__device__ __forceinline__ uint32_t pack_h2(__half a, __half b) {
    __half2 t; t.x = a; t.y = b;
    return *reinterpret_cast<uint32_t*>(&t);
}
__device__ __forceinline__ float sigmoidf_(float x) {
    return 1.f / (1.f + __expf(-x));
}

// ---------------- fused prep (B) + convert (A fp32->fp16, zero-pad) ----------------
__global__ void prep_convert_kernel(const float* __restrict__ att,
                                    const float* __restrict__ Wlin,
                                    const float* __restrict__ feat, int N) {
    if (blockIdx.x < PREP_BLOCKS) {
        int i = blockIdx.x * blockDim.x + threadIdx.x;    // [g][d][h] flat
        int g = i >> 16, d = (i >> 7) & 511, n = i & 127;
        float w = att[g * D_IN + d] * Wlin[i];
        g_Bh[(size_t)g * (HDIM * D_IN) + (size_t)n * D_IN + d] = __float2half_rn(w);
        return;
    }
    size_t i = ((size_t)(blockIdx.x - PREP_BLOCKS) * blockDim.x + threadIdx.x) * 8;
    if (i >= (size_t)NPAD * D_IN) return;
    uint4 v = make_uint4(0u, 0u, 0u, 0u);
    if (i < (size_t)N * D_IN) {
        float4 a = *reinterpret_cast<const float4*>(feat + i);
        float4 b = *reinterpret_cast<const float4*>(feat + i + 4);
        v = make_uint4(pack_h2(__float2half_rn(a.x), __float2half_rn(a.y)),
                       pack_h2(__float2half_rn(a.z), __float2half_rn(a.w)),
                       pack_h2(__float2half_rn(b.x), __float2half_rn(b.y)),
                       pack_h2(__float2half_rn(b.z), __float2half_rn(b.w)));
    }
    *reinterpret_cast<uint4*>(g_feat_h + i) = v;
}

// ---------------- GEMM: 256 thr, 2(m)x4(n) warps, warp tile m64n32, cp.async 3-stage ----
// stage: A 128x80B = 10240 | B 128x80B = 10240 -> 20480/stage, 3 stages = 61440 B
#define STG_SZ 20480
#define T_B    10240
#define SM_SZ  (3 * STG_SZ)

__global__ __launch_bounds__(256, 2)
void gemm_kernel(const float* __restrict__ b_lin,
                 const float* __restrict__ w_al, const float* __restrict__ b_al,
                 const float* __restrict__ w_ar, const float* __restrict__ b_ar,
                 float* __restrict__ out_hidden, int N) {
    extern __shared__ __align__(16) char sm[];
    const uint32_t sb = smem_u32(sm);

    const int tid = threadIdx.x, wid = tid >> 5, lid = tid & 31;
    const int wm = wid & 1, wn = wid >> 1;          // warp grid 2(m) x 4(n)
    const int g = blockIdx.x;
    const int row0 = blockIdx.y * BM;

    // loader mapping: unit u -> (row = u>>2, 16B quarter q = u&3); 512 units per tile
    const int lr0 = tid >> 2, lq = tid & 3;
    const __half* asrc = g_feat_h + (size_t)(row0 + lr0) * D_IN + lq * 8;
    const __half* asrc2 = asrc + (size_t)64 * D_IN;                 // rows 64..127
    const __half* bsrc = g_Bh + (size_t)g * (HDIM * D_IN) + (size_t)lr0 * D_IN + lq * 8;
    const __half* bsrc2 = bsrc + (size_t)64 * D_IN;
    const uint32_t dA1 = (uint32_t)lr0 * ASTRB + (uint32_t)lq * 16;
    const uint32_t dA2 = dA1 + 64 * ASTRB;

    auto issue = [&](int kchunk, uint32_t base) {
        int ko = kchunk * KC;
        cp16(base + dA1,       asrc  + ko);
        cp16(base + dA2,       asrc2 + ko);
        cp16(base + T_B + dA1, bsrc  + ko);
        cp16(base + T_B + dA2, bsrc2 + ko);
    };

    // preload stages 0,1
    issue(0, sb);            CP_COMMIT();
    issue(1, sb + STG_SZ);   CP_COMMIT();

    float c[4][4][4];
#pragma unroll
    for (int mi = 0; mi < 4; mi++)
#pragma unroll
        for (int ni = 0; ni < 4; ni++)
#pragma unroll
            for (int j = 0; j < 4; j++) c[mi][ni][j] = 0.f;

    const uint32_t lrs = (uint32_t)(lid & 15);      // ldmatrix row select
    const uint32_t lkh = (uint32_t)(lid >> 4) * 16; // k half offset (bytes)

    int bufidx = 0;
    for (int it = 0; it < NIT; it++) {
        CP_WAIT1();
        __syncthreads();
        const uint32_t cur = sb + (uint32_t)bufidx * STG_SZ;
        // issue stage it+2 into the buffer freed at iter it-1 (hidden under MMA below)
        if (it + 2 < NIT) {
            int nb = bufidx + 2; if (nb >= 3) nb -= 3;
            issue(it + 2, sb + (uint32_t)nb * STG_SZ);
        }
        CP_COMMIT();                                 // uniform group counting (may be empty)
        // compute: 2 ksteps of 16
#pragma unroll
        for (int ks = 0; ks < 2; ks++) {
            const uint32_t koff = (uint32_t)ks * 32 + lkh;
            uint32_t aA[4][4];
#pragma unroll
            for (int mi = 0; mi < 4; mi++) {
                uint32_t ra = (uint32_t)(wm * 64 + mi * 16) + lrs;
                ldsm4(aA[mi][0], aA[mi][1], aA[mi][2], aA[mi][3],
                      cur + ra * ASTRB + koff);
            }
            uint32_t bB[4][2];
#pragma unroll
            for (int p = 0; p < 2; p++) {
                uint32_t rb = (uint32_t)(wn * 32 + p * 16) + lrs;
                uint32_t r0, r1, r2, r3;
                ldsm4(r0, r1, r2, r3, cur + T_B + rb * ASTRB + koff);
                bB[2 * p][0] = r0; bB[2 * p][1] = r2;
                bB[2 * p + 1][0] = r1; bB[2 * p + 1][1] = r3;
            }
#pragma unroll
            for (int mi = 0; mi < 4; mi++)
#pragma unroll
                for (int ni = 0; ni < 4; ni++)
                    mma16816(c[mi][ni], aA[mi], bB[ni][0], bB[ni][1]);
        }
        if (++bufidx == 3) bufidx = 0;
    }

    // ---------------- epilogue ----------------
    __syncthreads();                    // all LDSM done; reuse smem for reductions
    float* laR = reinterpret_cast<float*>(sm);            // [4][128]
    float* raR = reinterpret_cast<float*>(sm + 2048);

    const int quad = lid >> 2, tq = lid & 3;
    const float* bl  = b_lin + g * HDIM;
    const float* wal = w_al + g * HDIM;
    const float* war = w_ar + g * HDIM;

#pragma unroll
    for (int mi = 0; mi < 4; mi++)
#pragma unroll
        for (int h = 0; h < 2; h++) {
            int rl = wm * 64 + mi * 16 + h * 8 + quad;
            int rg = row0 + rl;
            bool ok = rg < N;
            float la = 0.f, ra = 0.f;
            float* dst = out_hidden + (size_t)rg * (GDIM * HDIM) + g * HDIM;
#pragma unroll
            for (int ni = 0; ni < 4; ni++) {
                int col = wn * 32 + ni * 8 + tq * 2;
                float v0 = c[mi][ni][h * 2 + 0] + __ldg(bl + col);
                float v1 = c[mi][ni][h * 2 + 1] + __ldg(bl + col + 1);
                la += v0 * __ldg(wal + col) + v1 * __ldg(wal + col + 1);
                ra += v0 * __ldg(war + col) + v1 * __ldg(war + col + 1);
                if (ok) *reinterpret_cast<float2*>(dst + col) = make_float2(v0, v1);
            }
            la += __shfl_xor_sync(0xffffffffu, la, 1);
            la += __shfl_xor_sync(0xffffffffu, la, 2);
            ra += __shfl_xor_sync(0xffffffffu, ra, 1);
            ra += __shfl_xor_sync(0xffffffffu, ra, 2);
            if (tq == 0) { laR[wn * 128 + rl] = la; raR[wn * 128 + rl] = ra; }
        }
    __syncthreads();
    if (tid < 128) {
        int rg = row0 + tid;
        if (rg < N) {
            float la = laR[tid] + laR[128 + tid] + laR[256 + tid] + laR[384 + tid];
            float ra = raR[tid] + raR[128 + tid] + raR[256 + tid] + raR[384 + tid];
            reinterpret_cast<float*>(g_al)[rg * 4 + g] = la + b_al[g];
            reinterpret_cast<float*>(g_ar)[rg * 4 + g] = ra + b_ar[g];
        }
    }
}

// ---------------- edge factors: 2 edges/thread, vectorized, one-pass grid ----------------
__global__ void edge_kernel(const int* __restrict__ src,
                            const int* __restrict__ dst,
                            float* __restrict__ factors, int E, int N) {
    const size_t P = (size_t)E >> 1;                 // edge pairs
    const size_t stride = (size_t)gridDim.x * blockDim.x;
    for (size_t p = (size_t)blockIdx.x * blockDim.x + threadIdx.x; p < P; p += stride) {
        int2 s2 = reinterpret_cast<const int2*>(src)[p];
        int2 d2 = reinterpret_cast<const int2*>(dst)[p];
        int s0 = min(max(s2.x, 0), N - 1), s1 = min(max(s2.y, 0), N - 1);
        int d0 = min(max(d2.x, 0), N - 1), d1 = min(max(d2.y, 0), N - 1);
        float4 l0 = g_al[s0], l1 = g_al[s1];
        float4 r0 = g_ar[d0], r1 = g_ar[d1];
        size_t e = p * 2;
        reinterpret_cast<float2*>(factors + e)[0] =
            make_float2(sigmoidf_(l0.x + r0.x), sigmoidf_(l1.x + r1.x));
        reinterpret_cast<float2*>(factors + (size_t)E + e)[0] =
            make_float2(sigmoidf_(l0.y + r0.y), sigmoidf_(l1.y + r1.y));
        reinterpret_cast<float2*>(factors + (size_t)2 * E + e)[0] =
            make_float2(sigmoidf_(l0.z + r0.z), sigmoidf_(l1.z + r1.z));
        reinterpret_cast<float2*>(factors + (size_t)3 * E + e)[0] =
            make_float2(sigmoidf_(l0.w + r0.w), sigmoidf_(l1.w + r1.w));
    }
    // odd-E tail (defensive; E is even in this dataset)
    if ((E & 1) && blockIdx.x == 0 && threadIdx.x == 0) {
        int e = E - 1;
        int s = min(max(src[e], 0), N - 1);
        int d = min(max(dst[e], 0), N - 1);
        float4 l = g_al[s], r = g_ar[d];
        factors[e]                 = sigmoidf_(l.x + r.x);
        factors[(size_t)E + e]     = sigmoidf_(l.y + r.y);
        factors[(size_t)2 * E + e] = sigmoidf_(l.z + r.z);
        factors[(size_t)3 * E + e] = sigmoidf_(l.w + r.w);
    }
}

// ---------------- launch ----------------
extern "C" void kernel_launch(void* const* d_in, const int* in_sizes, int n_in,
                              void* d_out, int out_size) {
    const float* feat  = (const float*)d_in[0];
    const int*   src   = (const int*)d_in[1];
    const int*   dst   = (const int*)d_in[2];
    const float* att   = (const float*)d_in[3];
    const float* Wlin  = (const float*)d_in[4];
    const float* b_lin = (const float*)d_in[5];
    const float* w_al  = (const float*)d_in[6];
    const float* b_al  = (const float*)d_in[7];
    const float* w_ar  = (const float*)d_in[8];
    const float* b_ar  = (const float*)d_in[9];

    int N = in_sizes[0] / D_IN;
    int E = in_sizes[1];
    float* out     = (float*)d_out;
    float* factors = out + (size_t)N * (GDIM * HDIM);

    cudaFuncSetAttribute(gemm_kernel, cudaFuncAttributeMaxDynamicSharedMemorySize, SM_SZ);

    prep_convert_kernel<<<PREP_BLOCKS + CONV_BLOCKS, 256>>>(att, Wlin, feat, N);

    dim3 grid(GDIM, (NPAD + BM - 1) / BM);   // g fastest: CTAs sharing feat rows adjacent in wave
    gemm_kernel<<<grid, 256, SM_SZ>>>(b_lin, w_al, b_al, w_ar, b_ar, out, N);

    edge_kernel<<<6400, 256>>>(src, dst, factors, E, N);
}

// round 17
// speedup vs baseline: 1.0417x; 1.0096x over previous
#include <cuda_runtime.h>
#include <cuda_fp16.h>
#include <cstdint>

// GraphLearning, R17: convert pass folded into the GEMM.
//  - GEMM cp.async's fp32 A (3-stage), bulk-converts each chunk smem->smem into a
//    double-buffered fp16 tile (convert-for-next-iter => still ONE barrier/iter).
//  - removes the 44us standalone convert kernel; feat read exactly once.
// hidden_cat = feat @ B, B[d, g*128+h] = att[g,d]*Wlin[g,d,h]; a_l/a_r fused in epilogue.

#define NMAX   100000
#define NPAD   100096           // 782 * 128
#define D_IN   512
#define GDIM   4
#define HDIM   128
#define BM     128
#define KC     32
#define NIT    (D_IN / KC)      // 16
#define ASTRB  80               // fp16 tile row stride bytes -> conflict-free ldmatrix
#define A32STR 144              // fp32 stage row stride bytes -> conflict-free LDS.128

__device__ __half g_Bh[GDIM * HDIM * D_IN];          // B pre-transposed [g][n][k] fp16
__device__ float4 g_al[NMAX];
__device__ float4 g_ar[NMAX];

// ---------------- helpers ----------------
__device__ __forceinline__ uint32_t smem_u32(const void* p) {
    uint32_t a;
    asm("{ .reg .u64 t; cvta.to.shared.u64 t, %1; cvt.u32.u64 %0, t; }" : "=r"(a) : "l"(p));
    return a;
}
__device__ __forceinline__ void ldsm4(uint32_t& r0, uint32_t& r1, uint32_t& r2, uint32_t& r3,
                                      uint32_t addr) {
    asm volatile("ldmatrix.sync.aligned.m8n8.x4.shared.b16 {%0,%1,%2,%3}, [%4];"
                 : "=r"(r0), "=r"(r1), "=r"(r2), "=r"(r3) : "r"(addr));
}
__device__ __forceinline__ void mma16816(float* c, const uint32_t* a, uint32_t b0, uint32_t b1) {
    asm volatile("mma.sync.aligned.m16n8k16.row.col.f32.f16.f16.f32 "
                 "{%0,%1,%2,%3}, {%4,%5,%6,%7}, {%8,%9}, {%0,%1,%2,%3};"
                 : "+f"(c[0]), "+f"(c[1]), "+f"(c[2]), "+f"(c[3])
                 : "r"(a[0]), "r"(a[1]), "r"(a[2]), "r"(a[3]), "r"(b0), "r"(b1));
}
__device__ __forceinline__ void cp16(uint32_t dst, const void* src) {
    asm volatile("cp.async.cg.shared.global [%0], [%1], 16;" :: "r"(dst), "l"(src));
}
__device__ __forceinline__ void cp16z(uint32_t dst, const void* src, int sz) {
    asm volatile("cp.async.cg.shared.global [%0], [%1], 16, %2;"
                 :: "r"(dst), "l"(src), "r"(sz));
}
#define CP_COMMIT() asm volatile("cp.async.commit_group;" ::: "memory")
#define CP_WAIT1()  asm volatile("cp.async.wait_group 1;" ::: "memory")

__device__ __forceinline__ uint32_t pack_h2f(float a, float b) {
    __half2 h = __floats2half2_rn(a, b);
    return *reinterpret_cast<uint32_t*>(&h);
}
__device__ __forceinline__ float sigmoidf_(float x) {
    return 1.f / (1.f + __expf(-x));
}

// ---------------- prep: fold att, fp16 round, transpose to [n][k] ----------------
__global__ void prep_kernel(const float* __restrict__ att,
                            const float* __restrict__ Wlin) {
    int i = blockIdx.x * blockDim.x + threadIdx.x;    // [g][d][h] flat
    if (i >= GDIM * D_IN * HDIM) return;
    int g = i >> 16, d = (i >> 7) & 511, n = i & 127;
    float w = att[g * D_IN + d] * Wlin[i];
    g_Bh[(size_t)g * (HDIM * D_IN) + (size_t)n * D_IN + d] = __float2half_rn(w);
}

// ---------------- smem layout ----------------
#define A32_SZ (128 * A32STR)                 // 18432
#define A16_SZ (128 * ASTRB)                  // 10240
#define B_SZ   (128 * ASTRB)                  // 10240
#define OFF_A32(s) ((uint32_t)(s) * A32_SZ)                        // 3 stages
#define OFF_A16(s) (3 * A32_SZ + (uint32_t)(s) * A16_SZ)           // 2 buffers
#define OFF_B(s)   (3 * A32_SZ + 2 * A16_SZ + (uint32_t)(s) * B_SZ) // 3 stages
#define SM_SZ      (3 * A32_SZ + 2 * A16_SZ + 3 * B_SZ)            // 106496

// ---------------- GEMM: 256 thr, 2(m)x4(n) warps, warp tile m64n32 ----------------
__global__ __launch_bounds__(256, 2)
void gemm_kernel(const float* __restrict__ feat,
                 const float* __restrict__ b_lin,
                 const float* __restrict__ w_al, const float* __restrict__ b_al,
                 const float* __restrict__ w_ar, const float* __restrict__ b_ar,
                 float* __restrict__ out_hidden, int N) {
    extern __shared__ __align__(16) char sm[];
    const uint32_t sb = smem_u32(sm);

    const int tid = threadIdx.x, wid = tid >> 5, lid = tid & 31;
    const int wm = wid & 1, wn = wid >> 1;          // warp grid 2(m) x 4(n)
    const int g = blockIdx.x;
    const int row0 = blockIdx.y * BM;

    // ---- A32 loader: 1024 16B-units (128 rows x 8 quarters), 4 units/thread ----
    const float* asrc_j[4]; int asz_j[4]; uint32_t adst_j[4];
#pragma unroll
    for (int j = 0; j < 4; j++) {
        int u = tid + j * 256;
        int row = u >> 3, q = u & 7;
        int grow = row0 + row;
        asrc_j[j] = feat + (size_t)(grow < N ? grow : N - 1) * D_IN + q * 4;
        asz_j[j]  = (grow < N) ? 16 : 0;
        adst_j[j] = (uint32_t)row * A32STR + (uint32_t)q * 16;
    }
    // ---- B loader: 512 units (128 rows x 4 quarters), 2 units/thread ----
    const int blr = tid >> 2, blq = tid & 3;
    const __half* bsrc  = g_Bh + (size_t)g * (HDIM * D_IN) + (size_t)blr * D_IN + blq * 8;
    const __half* bsrc2 = bsrc + (size_t)64 * D_IN;
    const uint32_t dB1 = (uint32_t)blr * ASTRB + (uint32_t)blq * 16;
    const uint32_t dB2 = dB1 + 64 * ASTRB;

    auto issueA = [&](int kc, int s) {
        uint32_t base = sb + OFF_A32(s);
        int ko = kc * KC;
#pragma unroll
        for (int j = 0; j < 4; j++)
            cp16z(base + adst_j[j], asrc_j[j] + ko, asz_j[j]);
    };
    auto issueB = [&](int kc) {
        uint32_t base = sb + OFF_B(kc % 3);
        int ko = kc * KC;
        cp16(base + dB1, bsrc  + ko);
        cp16(base + dB2, bsrc2 + ko);
    };
    // ---- converter: A32 stage s -> A16 buffer d (bulk, conflict-free both sides) ----
    const int cr = tid & 127, ch = tid >> 7;
    auto convert = [&](int s, int d) {
        const float4* src = reinterpret_cast<const float4*>(
            sm + OFF_A32(s) + (uint32_t)cr * A32STR + (uint32_t)ch * 64);
        uint4* dst = reinterpret_cast<uint4*>(
            sm + OFF_A16(d) + (uint32_t)cr * ASTRB + (uint32_t)ch * 32);
        float4 v0 = src[0], v1 = src[1], v2 = src[2], v3 = src[3];
        dst[0] = make_uint4(pack_h2f(v0.x, v0.y), pack_h2f(v0.z, v0.w),
                            pack_h2f(v1.x, v1.y), pack_h2f(v1.z, v1.w));
        dst[1] = make_uint4(pack_h2f(v2.x, v2.y), pack_h2f(v2.z, v2.w),
                            pack_h2f(v3.x, v3.y), pack_h2f(v3.z, v3.w));
    };

    // ---- prologue: groups P0={A32 0}, P1={A32 1, B 0}; convert chunk 0; P2 ----
    issueA(0, 0);               CP_COMMIT();
    issueA(1, 1); issueB(0);    CP_COMMIT();
    CP_WAIT1();                 // P0 complete
    __syncthreads();
    convert(0, 0);
    issueA(2, 2); issueB(1);    CP_COMMIT();   // P2

    float c[4][4][4];
#pragma unroll
    for (int mi = 0; mi < 4; mi++)
#pragma unroll
        for (int ni = 0; ni < 4; ni++)
#pragma unroll
            for (int j = 0; j < 4; j++) c[mi][ni][j] = 0.f;

    const uint32_t lrs = (uint32_t)(lid & 15);      // ldmatrix row select
    const uint32_t lkh = (uint32_t)(lid >> 4) * 16; // k half offset (bytes)

    // group invariant at iter top: outstanding = P_{it+1}, P_{it+2}
    for (int it = 0; it < NIT; it++) {
        CP_WAIT1();                  // P_{it+1} complete: {A32[it+1], B[it]} (B[it] in P_it, done earlier)
        __syncthreads();             // orders: cp.async data, A16 reuse, A32 reuse
        if (it + 1 < NIT) convert((it + 1) % 3, (it + 1) & 1);
        if (it + 3 < NIT) issueA(it + 3, (it + 3) % 3);
        if (it + 2 < NIT) issueB(it + 2);
        CP_COMMIT();                 // uniform group counting (may be empty)

        const uint32_t aBase = sb + OFF_A16(it & 1);
        const uint32_t bBase = sb + OFF_B(it % 3);
#pragma unroll
        for (int ks = 0; ks < 2; ks++) {
            const uint32_t koff = (uint32_t)ks * 32 + lkh;
            uint32_t aA[4][4];
#pragma unroll
            for (int mi = 0; mi < 4; mi++) {
                uint32_t ra = (uint32_t)(wm * 64 + mi * 16) + lrs;
                ldsm4(aA[mi][0], aA[mi][1], aA[mi][2], aA[mi][3],
                      aBase + ra * ASTRB + koff);
            }
            uint32_t bB[4][2];
#pragma unroll
            for (int p = 0; p < 2; p++) {
                uint32_t rb = (uint32_t)(wn * 32 + p * 16) + lrs;
                uint32_t r0, r1, r2, r3;
                ldsm4(r0, r1, r2, r3, bBase + rb * ASTRB + koff);
                bB[2 * p][0] = r0; bB[2 * p][1] = r2;
                bB[2 * p + 1][0] = r1; bB[2 * p + 1][1] = r3;
            }
#pragma unroll
            for (int mi = 0; mi < 4; mi++)
#pragma unroll
                for (int ni = 0; ni < 4; ni++)
                    mma16816(c[mi][ni], aA[mi], bB[ni][0], bB[ni][1]);
        }
    }

    // ---------------- epilogue ----------------
    __syncthreads();                    // all LDSM done; reuse smem for reductions
    float* laR = reinterpret_cast<float*>(sm);            // [4][128]
    float* raR = reinterpret_cast<float*>(sm + 2048);

    const int quad = lid >> 2, tq = lid & 3;
    const float* bl  = b_lin + g * HDIM;
    const float* wal = w_al + g * HDIM;
    const float* war = w_ar + g * HDIM;

#pragma unroll
    for (int mi = 0; mi < 4; mi++)
#pragma unroll
        for (int h = 0; h < 2; h++) {
            int rl = wm * 64 + mi * 16 + h * 8 + quad;
            int rg = row0 + rl;
            bool ok = rg < N;
            float la = 0.f, ra = 0.f;
            float* dst = out_hidden + (size_t)rg * (GDIM * HDIM) + g * HDIM;
#pragma unroll
            for (int ni = 0; ni < 4; ni++) {
                int col = wn * 32 + ni * 8 + tq * 2;
                float v0 = c[mi][ni][h * 2 + 0] + __ldg(bl + col);
                float v1 = c[mi][ni][h * 2 + 1] + __ldg(bl + col + 1);
                la += v0 * __ldg(wal + col) + v1 * __ldg(wal + col + 1);
                ra += v0 * __ldg(war + col) + v1 * __ldg(war + col + 1);
                if (ok) *reinterpret_cast<float2*>(dst + col) = make_float2(v0, v1);
            }
            la += __shfl_xor_sync(0xffffffffu, la, 1);
            la += __shfl_xor_sync(0xffffffffu, la, 2);
            ra += __shfl_xor_sync(0xffffffffu, ra, 1);
            ra += __shfl_xor_sync(0xffffffffu, ra, 2);
            if (tq == 0) { laR[wn * 128 + rl] = la; raR[wn * 128 + rl] = ra; }
        }
    __syncthreads();
    if (tid < 128) {
        int rg = row0 + tid;
        if (rg < N) {
            float la = laR[tid] + laR[128 + tid] + laR[256 + tid] + laR[384 + tid];
            float ra = raR[tid] + raR[128 + tid] + raR[256 + tid] + raR[384 + tid];
            reinterpret_cast<float*>(g_al)[rg * 4 + g] = la + b_al[g];
            reinterpret_cast<float*>(g_ar)[rg * 4 + g] = ra + b_ar[g];
        }
    }
}

// ---------------- edge factors: 2 edges/thread, vectorized, one-pass grid ----------------
__global__ void edge_kernel(const int* __restrict__ src,
                            const int* __restrict__ dst,
                            float* __restrict__ factors, int E, int N) {
    const size_t P = (size_t)E >> 1;                 // edge pairs
    const size_t stride = (size_t)gridDim.x * blockDim.x;
    for (size_t p = (size_t)blockIdx.x * blockDim.x + threadIdx.x; p < P; p += stride) {
        int2 s2 = reinterpret_cast<const int2*>(src)[p];
        int2 d2 = reinterpret_cast<const int2*>(dst)[p];
        int s0 = min(max(s2.x, 0), N - 1), s1 = min(max(s2.y, 0), N - 1);
        int d0 = min(max(d2.x, 0), N - 1), d1 = min(max(d2.y, 0), N - 1);
        float4 l0 = g_al[s0], l1 = g_al[s1];
        float4 r0 = g_ar[d0], r1 = g_ar[d1];
        size_t e = p * 2;
        reinterpret_cast<float2*>(factors + e)[0] =
            make_float2(sigmoidf_(l0.x + r0.x), sigmoidf_(l1.x + r1.x));
        reinterpret_cast<float2*>(factors + (size_t)E + e)[0] =
            make_float2(sigmoidf_(l0.y + r0.y), sigmoidf_(l1.y + r1.y));
        reinterpret_cast<float2*>(factors + (size_t)2 * E + e)[0] =
            make_float2(sigmoidf_(l0.z + r0.z), sigmoidf_(l1.z + r1.z));
        reinterpret_cast<float2*>(factors + (size_t)3 * E + e)[0] =
            make_float2(sigmoidf_(l0.w + r0.w), sigmoidf_(l1.w + r1.w));
    }
    if ((E & 1) && blockIdx.x == 0 && threadIdx.x == 0) {
        int e = E - 1;
        int s = min(max(src[e], 0), N - 1);
        int d = min(max(dst[e], 0), N - 1);
        float4 l = g_al[s], r = g_ar[d];
        factors[e]                 = sigmoidf_(l.x + r.x);
        factors[(size_t)E + e]     = sigmoidf_(l.y + r.y);
        factors[(size_t)2 * E + e] = sigmoidf_(l.z + r.z);
        factors[(size_t)3 * E + e] = sigmoidf_(l.w + r.w);
    }
}

// ---------------- launch ----------------
extern "C" void kernel_launch(void* const* d_in, const int* in_sizes, int n_in,
                              void* d_out, int out_size) {
    const float* feat  = (const float*)d_in[0];
    const int*   src   = (const int*)d_in[1];
    const int*   dst   = (const int*)d_in[2];
    const float* att   = (const float*)d_in[3];
    const float* Wlin  = (const float*)d_in[4];
    const float* b_lin = (const float*)d_in[5];
    const float* w_al  = (const float*)d_in[6];
    const float* b_al  = (const float*)d_in[7];
    const float* w_ar  = (const float*)d_in[8];
    const float* b_ar  = (const float*)d_in[9];

    int N = in_sizes[0] / D_IN;
    int E = in_sizes[1];
    float* out     = (float*)d_out;
    float* factors = out + (size_t)N * (GDIM * HDIM);

    cudaFuncSetAttribute(gemm_kernel, cudaFuncAttributeMaxDynamicSharedMemorySize, SM_SZ);

    prep_kernel<<<1024, 256>>>(att, Wlin);

    dim3 grid(GDIM, (NPAD + BM - 1) / BM);   // g fastest: 4 CTAs share each feat tile via L2
    gemm_kernel<<<grid, 256, SM_SZ>>>(feat, b_lin, w_al, b_al, w_ar, b_ar, out, N);

    edge_kernel<<<6400, 256>>>(src, dst, factors, E, N);
}